// round 14
// baseline (speedup 1.0000x reference)
#include <cuda_runtime.h>
#include <math.h>
#include <stdint.h>

// ---------------- problem constants ----------------
#define NROWS  4096
#define DDIM   256
#define KMEM   16384
#define ZCOLS  4096
#define WROWS  (ZCOLS + KMEM)   // 20480
#define LSEQ   256
#define SPLITS 9                // 160 col tiles of 128: 7x18 + 2x17
#define TMR    128
#define TNC    128
#define WPR    128              // words per row (bf16 packed)
#define SA     132              // A smem stride (words); ==4 mod 32
#define INV_T  (1.0f/0.07f)
#define LOG2E  1.4426950408889634f
#define LN2F   0.6931471805599453f
#define NEG_BIG (-1.0e30f)

#define SMEM_DYN (TMR * SA * 4)   // 67,584 B

// ---------------- scratch ----------------
__device__ uint32_t g_wp[(size_t)WROWS * WPR];
__device__ float g_pm[SPLITS * NROWS];
__device__ float g_ps[SPLITS * NROWS];
__device__ float g_bs[32];
__device__ unsigned int g_ctr;   // zero-init; self-resets each launch

// ---------------- helpers ----------------
__device__ __forceinline__ uint32_t packbf(float lo, float hi) {
    uint32_t r;
    asm("cvt.rn.bf16x2.f32 %0, %1, %2;" : "=r"(r) : "f"(hi), "f"(lo));
    return r;
}
__device__ __forceinline__ float ex2f(float x) {
    float r; asm("ex2.approx.f32 %0, %1;" : "=f"(r) : "f"(x)); return r;
}
__device__ __forceinline__ void mma16(float* d,
                                      uint32_t a0, uint32_t a1, uint32_t a2, uint32_t a3,
                                      uint32_t b0, uint32_t b1) {
    asm volatile(
        "mma.sync.aligned.m16n8k16.row.col.f32.bf16.bf16.f32 "
        "{%0,%1,%2,%3}, {%4,%5,%6,%7}, {%8,%9}, {%0,%1,%2,%3};"
        : "+f"(d[0]), "+f"(d[1]), "+f"(d[2]), "+f"(d[3])
        : "r"(a0), "r"(a1), "r"(a2), "r"(a3), "r"(b0), "r"(b1));
}

// ---------------------------------------------------------------------------
// Pre-pass (R12 version): bf16-convert z||mem into the lane-fragment layout.
// One thread per (row, chunk, half): 4 LDG.128 in, 2 STG.128 out.
// ---------------------------------------------------------------------------
__global__ __launch_bounds__(256)
void prep(const float* __restrict__ z, const float* __restrict__ mem) {
    const int idx = blockIdx.x * 256 + threadIdx.x;
    const int row = idx >> 4;
    const int ch  = (idx >> 1) & 7;
    const int h   = idx & 1;
    if (row >= WROWS) return;
    const float* src = ((row < ZCOLS) ? (z + (size_t)row * DDIM)
                                      : (mem + (size_t)(row - ZCOLS) * DDIM))
                       + ch * 32 + h * 4;
    float4 a0 = *(const float4*)(src);
    float4 a1 = *(const float4*)(src + 8);
    float4 a2 = *(const float4*)(src + 16);
    float4 a3 = *(const float4*)(src + 24);
    uint32_t* dst = g_wp + (size_t)row * WPR + ch * 16 + h * 8;
    uint4 o0, o1;
    o0.x = packbf(a0.x, a0.y);  o0.y = packbf(a1.x, a1.y);
    o0.z = packbf(a2.x, a2.y);  o0.w = packbf(a3.x, a3.y);
    o1.x = packbf(a0.z, a0.w);  o1.y = packbf(a1.z, a1.w);
    o1.z = packbf(a2.z, a2.w);  o1.w = packbf(a3.z, a3.w);
    *(uint4*)(dst)     = o0;
    *(uint4*)(dst + 4) = o1;
}

// ---------------------------------------------------------------------------
// Fused bf16 mma.sync GEMM + online logsumexp, software-pipelined epilogue.
// 256 threads = 8 warps, 2(M) x 4(N); warp tile 64x32 (m16n8k16), TWO acc
// buffers: while tile T+1's MMAs issue, tile T's epilogue executes one
// row-group per k-chunk in the tensor pipe's shadow. Barrier-free main loop.
// ---------------------------------------------------------------------------
__global__ __launch_bounds__(256, 1)
void lse_mma() {
    extern __shared__ uint32_t As[];    // [128][SA]
    __shared__ float red_m[8][64];
    __shared__ float red_s[8][64];

    const int tid  = threadIdx.x;
    const int wid  = tid >> 5;
    const int lane = tid & 31;
    const int wm   = wid >> 2;          // 0..1 (M)
    const int wn   = wid & 3;           // 0..3 (N)
    const int qr   = lane >> 2;         // 0..7
    const int qc   = lane & 3;          // 0..3
    const int m0   = blockIdx.x * TMR;
    const int s    = blockIdx.y;
    const int lo   = s * 17 + (s < 7 ? s : 7);
    const int nt   = (s < 7) ? 18 : 17;
    const int rot  = wm ? (nt >> 1) : 0;

    const int broff = wn * 32 + qr;
    const int bwoff = qc * 4;

    // first tile chunk-0 loads issued before the A copy (complete under it)
    int ti = rot;
    const uint32_t* bp = g_wp + (size_t)((lo + ti) * TNC + broff) * WPR + bwoff;
    uint4 bq[2][4];
    #pragma unroll
    for (int ni = 0; ni < 4; ++ni)
        bq[0][ni] = *(const uint4*)(bp + ni * 8 * WPR);

    // ---- A tile copy with quad remap ----
    #pragma unroll 4
    for (int it = 0; it < 16; ++it) {
        int idx = it * 256 + tid;
        int m   = idx >> 5;
        int kq  = idx & 31;
        int d   = kq & 7;
        int sq  = (kq & ~7) | (((d & 1) << 2) | (d >> 1));
        uint4 v = *(const uint4*)(g_wp + (size_t)(m0 + m) * WPR + sq * 4);
        *(uint4*)(As + m * SA + kq * 4) = v;
    }
    __syncthreads();                    // the ONLY barrier before the end

    float rm[8], rs[8];                 // per-lane online LSE state
    #pragma unroll
    for (int i = 0; i < 8; ++i) { rm[i] = NEG_BIG; rs[i] = 0.0f; }

    const float Cs = INV_T * LOG2E;
    float accA[4][4][4], accB[4][4][4];
    int  c0P = 0;
    bool dfP = false;

    // one epilogue row-group (g = mi*2+h) of the PREVIOUS tile, lane-local
    auto epi_slice = [&](float (&P)[4][4][4], int g) {
        const int mi = g >> 1, h = g & 1;
        float mx = NEG_BIG;
        #pragma unroll
        for (int ni = 0; ni < 4; ++ni)
            #pragma unroll
            for (int c = 0; c < 2; ++c) {
                float x = P[mi][ni][h * 2 + c];
                if (dfP) {
                    const int gcol = c0P + wn * 32 + ni * 8 + 2 * qc + c;
                    const int grow = m0 + wm * 64 + mi * 16 + h * 8 + qr;
                    if (gcol == grow) x = NEG_BIG;
                }
                P[mi][ni][h * 2 + c] = x;
                mx = fmaxf(mx, x);
            }
        const float mxs = mx * Cs;
        float sc = 0.0f;
        #pragma unroll
        for (int ni = 0; ni < 4; ++ni)
            #pragma unroll
            for (int c = 0; c < 2; ++c)
                sc += ex2f(fmaf(P[mi][ni][h * 2 + c], Cs, -mxs));
        const float mn = fmaxf(rm[g], mxs);
        rs[g] = rs[g] * ex2f(rm[g] - mn) + sc * ex2f(mxs - mn);
        rm[g] = mn;
    };

    // GEMM of the current tile into `cur`; interleave prev-tile epilogue
    auto tile_step = [&](float (&cur)[4][4][4], float (&prev)[4][4][4],
                         bool doEpi) {
        const int c0 = (lo + ti) * TNC;
        int tn = ti + 1; if (tn >= nt) tn = 0;
        const uint32_t* bpn =
            g_wp + (size_t)((lo + tn) * TNC + broff) * WPR + bwoff;

        #pragma unroll
        for (int a = 0; a < 4; ++a)
            #pragma unroll
            for (int b = 0; b < 4; ++b)
                #pragma unroll
                for (int c = 0; c < 4; ++c) cur[a][b][c] = 0.0f;

        #pragma unroll
        for (int kc = 0; kc < 8; ++kc) {
            const int cb = kc & 1;
            if (kc < 7) {               // prefetch next chunk of this tile
                #pragma unroll
                for (int ni = 0; ni < 4; ++ni)
                    bq[cb ^ 1][ni] =
                        *(const uint4*)(bp + ni * 8 * WPR + (kc + 1) * 16);
            } else {                    // prefetch next tile's chunk 0
                #pragma unroll
                for (int ni = 0; ni < 4; ++ni)
                    bq[0][ni] = *(const uint4*)(bpn + ni * 8 * WPR);
            }
            const int ao = (kc >> 1) * 32 + qc * 8 + (kc & 1) * 4;
            uint4 aL[4], aH[4];
            #pragma unroll
            for (int mi = 0; mi < 4; ++mi) {
                const int r = wm * 64 + mi * 16 + qr;
                aL[mi] = *(const uint4*)(As + r * SA + ao);
                aH[mi] = *(const uint4*)(As + (r + 8) * SA + ao);
            }
            #pragma unroll
            for (int mi = 0; mi < 4; ++mi)
                #pragma unroll
                for (int ni = 0; ni < 4; ++ni)
                    mma16(cur[mi][ni], aL[mi].x, aH[mi].x, aL[mi].y, aH[mi].y,
                          bq[cb][ni].x, bq[cb][ni].y);
            #pragma unroll
            for (int mi = 0; mi < 4; ++mi)
                #pragma unroll
                for (int ni = 0; ni < 4; ++ni)
                    mma16(cur[mi][ni], aL[mi].z, aH[mi].z, aL[mi].w, aH[mi].w,
                          bq[cb][ni].z, bq[cb][ni].w);
            if (doEpi) epi_slice(prev, kc);   // runs in the MMA shadow
        }
        ti = tn; bp = bpn;
        c0P = c0; dfP = (c0 == m0);
    };

    tile_step(accA, accB, false);       // tile 0: no previous epilogue
    int tj = 1;
    for (; tj + 1 < nt; tj += 2) {
        tile_step(accB, accA, true);
        tile_step(accA, accB, true);
    }
    if (tj < nt) {                      // nt even: one tile left, ends in B
        tile_step(accB, accA, true);
        #pragma unroll
        for (int g = 0; g < 8; ++g) epi_slice(accB, g);
    } else {                            // nt odd: last tile ended in A
        #pragma unroll
        for (int g = 0; g < 8; ++g) epi_slice(accA, g);
    }

    // ---- merge the 4 qc-lanes' partial LSE states (2 butterfly steps) ----
    #pragma unroll
    for (int ri = 0; ri < 8; ++ri) {
        #pragma unroll
        for (int off = 1; off <= 2; off <<= 1) {
            float om = __shfl_xor_sync(0xffffffffu, rm[ri], off);
            float os = __shfl_xor_sync(0xffffffffu, rs[ri], off);
            float mn = fmaxf(rm[ri], om);
            rs[ri] = rs[ri] * ex2f(rm[ri] - mn) + os * ex2f(om - mn);
            rm[ri] = mn;
        }
    }

    // ---- cross-warp (N-dim) merge via smem ----
    if (qc == 0) {
        #pragma unroll
        for (int mi = 0; mi < 4; ++mi)
            #pragma unroll
            for (int h = 0; h < 2; ++h) {
                const int lrw = mi * 16 + h * 8 + qr;
                red_m[wid][lrw] = rm[mi * 2 + h];
                red_s[wid][lrw] = rs[mi * 2 + h];
            }
    }
    __syncthreads();
    if (tid < 128) {
        const int wmm = tid >> 6, ri = tid & 63;
        float m = red_m[wmm * 4][ri];
        #pragma unroll
        for (int w = 1; w < 4; ++w) m = fmaxf(m, red_m[wmm * 4 + w][ri]);
        float ss = 0.0f;
        #pragma unroll
        for (int w = 0; w < 4; ++w)
            ss += red_s[wmm * 4 + w][ri] * ex2f(red_m[wmm * 4 + w][ri] - m);
        g_pm[s * NROWS + m0 + tid] = m;
        g_ps[s * NROWS + m0 + tid] = ss;
    }
}

// ---------------------------------------------------------------------------
// Combine split partials -> lse -> per-pair -> per-block sum; the LAST block
// (atomic ticket) tree-reduces the 32 block sums and writes the loss.
// ---------------------------------------------------------------------------
__global__ void lse_finalize(const float* __restrict__ z, float* __restrict__ out) {
    __shared__ float sh[128];
    __shared__ unsigned int s_last;
    const int i = blockIdx.x * 128 + threadIdx.x;

    float m = g_pm[i];
    #pragma unroll
    for (int s2 = 1; s2 < SPLITS; ++s2)
        m = fmaxf(m, g_pm[s2 * NROWS + i]);
    float ss = 0.0f;
    #pragma unroll
    for (int s2 = 0; s2 < SPLITS; ++s2)
        ss += g_ps[s2 * NROWS + i] * ex2f(g_pm[s2 * NROWS + i] - m);
    const float lse = (m + log2f(ss)) * LN2F;

    const bool valid = (i < NROWS - 1) && ((i & (LSEQ - 1)) != (LSEQ - 1));
    float pp = 0.0f;
    if (valid) {
        const float4* a = (const float4*)(z + (size_t)i * DDIM);
        const float4* b = (const float4*)(z + (size_t)(i + 1) * DDIM);
        float d0 = 0.0f;
        #pragma unroll 8
        for (int k = 0; k < DDIM / 4; ++k) {
            float4 x = a[k], y = b[k];
            d0 = fmaf(x.x, y.x, d0);
            d0 = fmaf(x.y, y.y, d0);
            d0 = fmaf(x.z, y.z, d0);
            d0 = fmaf(x.w, y.w, d0);
        }
        pp = lse - d0 * INV_T;
    }

    sh[threadIdx.x] = pp;
    __syncthreads();
    #pragma unroll
    for (int o = 64; o > 0; o >>= 1) {
        if (threadIdx.x < o) sh[threadIdx.x] += sh[threadIdx.x + o];
        __syncthreads();
    }
    if (threadIdx.x == 0) {
        g_bs[blockIdx.x] = sh[0];
        __threadfence();
        s_last = (atomicAdd(&g_ctr, 1u) == 31u);
    }
    __syncthreads();
    if (s_last && threadIdx.x < 32) {
        float v = g_bs[threadIdx.x];
        #pragma unroll
        for (int o = 16; o > 0; o >>= 1)
            v += __shfl_xor_sync(0xffffffffu, v, o);
        if (threadIdx.x == 0) {
            out[0] = v * (1.0f / 4080.0f);
            g_ctr = 0;                   // reset for next graph replay
        }
    }
}

// ---------------------------------------------------------------------------
extern "C" void kernel_launch(void* const* d_in, const int* in_sizes, int n_in,
                              void* d_out, int out_size) {
    const float* z   = nullptr;
    const float* mem = nullptr;
    for (int i = 0; i < n_in; ++i) {
        if (in_sizes[i] == NROWS * DDIM && !z)   z   = (const float*)d_in[i];
        if (in_sizes[i] == KMEM * DDIM  && !mem) mem = (const float*)d_in[i];
    }
    if (!z)   z   = (const float*)d_in[0];
    if (!mem) mem = (const float*)d_in[2];

    cudaFuncSetAttribute(lse_mma, cudaFuncAttributeMaxDynamicSharedMemorySize,
                         SMEM_DYN);
    prep<<<(WROWS * 16 + 255) / 256, 256>>>(z, mem);
    lse_mma<<<dim3(32, SPLITS), 256, SMEM_DYN>>>();
    lse_finalize<<<32, 128>>>(z, (float*)d_out);
}

// round 15
// speedup vs baseline: 1.8971x; 1.8971x over previous
#include <cuda_runtime.h>
#include <math.h>
#include <stdint.h>

// ---------------- problem constants ----------------
#define NROWS  4096
#define DDIM   256
#define KMEM   16384
#define ZCOLS  4096
#define WROWS  (ZCOLS + KMEM)   // 20480
#define LSEQ   256
#define SPLITS 9                // 80 col tiles of 256: 8x9 + 1x8
#define TMR    128
#define TNC    256
#define WPR    128              // words per row (bf16 packed)
#define SA     132              // A smem stride (words); ==4 mod 32
#define INV_T  (1.0f/0.07f)
#define LOG2E  1.4426950408889634f
#define LN2F   0.6931471805599453f
#define NEG_BIG (-1.0e30f)

#define SMEM_DYN (TMR * SA * 4)   // 67,584 B

// ---------------- scratch ----------------
__device__ uint32_t g_wp[(size_t)WROWS * WPR];
__device__ float g_pm[SPLITS * NROWS];
__device__ float g_ps[SPLITS * NROWS];
__device__ float g_bs[32];
__device__ unsigned int g_ctr;   // zero-init; self-resets each launch

// ---------------- helpers ----------------
__device__ __forceinline__ uint32_t packbf(float lo, float hi) {
    uint32_t r;
    asm("cvt.rn.bf16x2.f32 %0, %1, %2;" : "=r"(r) : "f"(hi), "f"(lo));
    return r;
}
__device__ __forceinline__ float ex2f(float x) {
    float r; asm("ex2.approx.f32 %0, %1;" : "=f"(r) : "f"(x)); return r;
}
__device__ __forceinline__ void mma16(float* d,
                                      uint32_t a0, uint32_t a1, uint32_t a2, uint32_t a3,
                                      uint32_t b0, uint32_t b1) {
    asm volatile(
        "mma.sync.aligned.m16n8k16.row.col.f32.bf16.bf16.f32 "
        "{%0,%1,%2,%3}, {%4,%5,%6,%7}, {%8,%9}, {%0,%1,%2,%3};"
        : "+f"(d[0]), "+f"(d[1]), "+f"(d[2]), "+f"(d[3])
        : "r"(a0), "r"(a1), "r"(a2), "r"(a3), "r"(b0), "r"(b1));
}

// ---------------------------------------------------------------------------
// Pre-pass (R12 version — fastest measured): bf16-convert z||mem into the
// lane-fragment layout. One thread per (row, chunk, half).
// ---------------------------------------------------------------------------
__global__ __launch_bounds__(256)
void prep(const float* __restrict__ z, const float* __restrict__ mem) {
    const int idx = blockIdx.x * 256 + threadIdx.x;
    const int row = idx >> 4;
    const int ch  = (idx >> 1) & 7;
    const int h   = idx & 1;
    if (row >= WROWS) return;
    const float* src = ((row < ZCOLS) ? (z + (size_t)row * DDIM)
                                      : (mem + (size_t)(row - ZCOLS) * DDIM))
                       + ch * 32 + h * 4;
    float4 a0 = *(const float4*)(src);
    float4 a1 = *(const float4*)(src + 8);
    float4 a2 = *(const float4*)(src + 16);
    float4 a3 = *(const float4*)(src + 24);
    uint32_t* dst = g_wp + (size_t)row * WPR + ch * 16 + h * 8;
    uint4 o0, o1;
    o0.x = packbf(a0.x, a0.y);  o0.y = packbf(a1.x, a1.y);
    o0.z = packbf(a2.x, a2.y);  o0.w = packbf(a3.x, a3.y);
    o1.x = packbf(a0.z, a0.w);  o1.y = packbf(a1.z, a1.w);
    o1.z = packbf(a2.z, a2.w);  o1.w = packbf(a3.z, a3.w);
    *(uint4*)(dst)     = o0;
    *(uint4*)(dst + 4) = o1;
}

// ---------------------------------------------------------------------------
// Fused bf16 mma.sync GEMM + online logsumexp.
// 256 threads = 8 warps, 2(M) x 4(N); warp tile 64x64 (m16n8k16).
// Barrier-free main loop; SMSP-paired warps staggered by nt/2 tiles;
// split-pass MMA issue; lane-local epilogue (qc lanes merged once at end).
// ---------------------------------------------------------------------------
__global__ __launch_bounds__(256, 1)
void lse_mma() {
    extern __shared__ uint32_t As[];    // [128][SA]
    __shared__ float red_m[8][64];
    __shared__ float red_s[8][64];

    const int tid  = threadIdx.x;
    const int wid  = tid >> 5;
    const int lane = tid & 31;
    const int wm   = wid >> 2;          // 0..1 (M)
    const int wn   = wid & 3;           // 0..3 (N)
    const int qr   = lane >> 2;         // 0..7
    const int qc   = lane & 3;          // 0..3
    const int m0   = blockIdx.x * TMR;
    const int s    = blockIdx.y;
    const int lo   = s * 9;
    const int nt   = (s < 8) ? 9 : 8;
    const int rot  = wm ? (nt >> 1) : 0;

    const int broff = wn * 64 + qr;
    const int bwoff = qc * 4;

    // first tile chunk-0 loads issued before the A copy (complete under it)
    int ti = rot;
    const uint32_t* bp = g_wp + (size_t)((lo + ti) * TNC + broff) * WPR + bwoff;
    uint4 bq[2][8];
    #pragma unroll
    for (int ni = 0; ni < 8; ++ni)
        bq[0][ni] = *(const uint4*)(bp + ni * 8 * WPR);

    // ---- A tile copy with quad remap ----
    #pragma unroll 4
    for (int it = 0; it < 16; ++it) {
        int idx = it * 256 + tid;
        int m   = idx >> 5;
        int kq  = idx & 31;
        int d   = kq & 7;
        int sq  = (kq & ~7) | (((d & 1) << 2) | (d >> 1));
        uint4 v = *(const uint4*)(g_wp + (size_t)(m0 + m) * WPR + sq * 4);
        *(uint4*)(As + m * SA + kq * 4) = v;
    }
    __syncthreads();                    // the ONLY barrier before the end

    float rm[8], rs[8];                 // per-lane online LSE state
    #pragma unroll
    for (int i = 0; i < 8; ++i) { rm[i] = NEG_BIG; rs[i] = 0.0f; }

    const float Cs = INV_T * LOG2E;

    #pragma unroll 1
    for (int tj = 0; tj < nt; ++tj) {
        const int  c0 = (lo + ti) * TNC;
        const bool zp = (c0 < ZCOLS);

        int tn = ti + 1; if (tn >= nt) tn = 0;
        const uint32_t* bpn = g_wp + (size_t)((lo + tn) * TNC + broff) * WPR + bwoff;

        float acc[4][8][4];
        #pragma unroll
        for (int a = 0; a < 4; ++a)
            #pragma unroll
            for (int b = 0; b < 8; ++b)
                #pragma unroll
                for (int c = 0; c < 4; ++c) acc[a][b][c] = 0.0f;

        #pragma unroll 2
        for (int kc = 0; kc < 8; ++kc) {
            const int cur = kc & 1;
            if (kc < 7) {
                #pragma unroll
                for (int ni = 0; ni < 8; ++ni)
                    bq[cur ^ 1][ni] =
                        *(const uint4*)(bp + ni * 8 * WPR + (kc + 1) * 16);
            } else if (tj + 1 < nt) {
                #pragma unroll
                for (int ni = 0; ni < 8; ++ni)
                    bq[0][ni] = *(const uint4*)(bpn + ni * 8 * WPR);
            }
            const int ao = (kc >> 1) * 32 + qc * 8 + (kc & 1) * 4;
            uint4 aL[4], aH[4];
            #pragma unroll
            for (int mi = 0; mi < 4; ++mi) {
                const int r = wm * 64 + mi * 16 + qr;
                aL[mi] = *(const uint4*)(As + r * SA + ao);
                aH[mi] = *(const uint4*)(As + (r + 8) * SA + ao);
            }
            // pass 1: x/y halves — 32 MMAs on distinct accumulators
            #pragma unroll
            for (int mi = 0; mi < 4; ++mi)
                #pragma unroll
                for (int ni = 0; ni < 8; ++ni)
                    mma16(acc[mi][ni], aL[mi].x, aH[mi].x, aL[mi].y, aH[mi].y,
                          bq[cur][ni].x, bq[cur][ni].y);
            // pass 2: z/w halves — RAW distance on each acc is 32 issues
            #pragma unroll
            for (int mi = 0; mi < 4; ++mi)
                #pragma unroll
                for (int ni = 0; ni < 8; ++ni)
                    mma16(acc[mi][ni], aL[mi].z, aH[mi].z, aL[mi].w, aH[mi].w,
                          bq[cur][ni].z, bq[cur][ni].w);
        }

        // ---- lane-local flash-LSE epilogue: NO shuffles ----
        const bool dflag = zp && (c0 == (m0 & ~(TNC - 1)));
        #pragma unroll
        for (int mi = 0; mi < 4; ++mi) {
            #pragma unroll
            for (int h = 0; h < 2; ++h) {
                const int lr   = wm * 64 + mi * 16 + h * 8 + qr;
                const int grow = m0 + lr;
                float v[16];
                float mx = NEG_BIG;
                #pragma unroll
                for (int ni = 0; ni < 8; ++ni) {
                    #pragma unroll
                    for (int c = 0; c < 2; ++c) {
                        float x = acc[mi][ni][h * 2 + c];
                        if (dflag) {
                            const int gcol = c0 + wn * 64 + ni * 8 + 2 * qc + c;
                            if (gcol == grow) x = NEG_BIG;
                        }
                        v[ni * 2 + c] = x;
                        mx = fmaxf(mx, x);
                    }
                }
                const float mxs = mx * Cs;
                float sc = 0.0f;
                #pragma unroll
                for (int j = 0; j < 16; ++j)
                    sc += ex2f(fmaf(v[j], Cs, -mxs));
                const int ri = mi * 2 + h;
                const float mn = fmaxf(rm[ri], mxs);
                rs[ri] = rs[ri] * ex2f(rm[ri] - mn) + sc * ex2f(mxs - mn);
                rm[ri] = mn;
            }
        }

        ti = tn;
        bp = bpn;
    }

    // ---- merge the 4 qc-lanes' partial LSE states (2 butterfly steps) ----
    #pragma unroll
    for (int ri = 0; ri < 8; ++ri) {
        #pragma unroll
        for (int off = 1; off <= 2; off <<= 1) {
            float om = __shfl_xor_sync(0xffffffffu, rm[ri], off);
            float os = __shfl_xor_sync(0xffffffffu, rs[ri], off);
            float mn = fmaxf(rm[ri], om);
            rs[ri] = rs[ri] * ex2f(rm[ri] - mn) + os * ex2f(om - mn);
            rm[ri] = mn;
        }
    }

    // ---- cross-warp (N-dim) merge via smem ----
    if (qc == 0) {
        #pragma unroll
        for (int mi = 0; mi < 4; ++mi)
            #pragma unroll
            for (int h = 0; h < 2; ++h) {
                const int lrw = mi * 16 + h * 8 + qr;
                red_m[wid][lrw] = rm[mi * 2 + h];
                red_s[wid][lrw] = rs[mi * 2 + h];
            }
    }
    __syncthreads();
    if (tid < 128) {
        const int wmm = tid >> 6, ri = tid & 63;
        float m = red_m[wmm * 4][ri];
        #pragma unroll
        for (int w = 1; w < 4; ++w) m = fmaxf(m, red_m[wmm * 4 + w][ri]);
        float ss = 0.0f;
        #pragma unroll
        for (int w = 0; w < 4; ++w)
            ss += red_s[wmm * 4 + w][ri] * ex2f(red_m[wmm * 4 + w][ri] - m);
        g_pm[s * NROWS + m0 + tid] = m;
        g_ps[s * NROWS + m0 + tid] = ss;
    }
}

// ---------------------------------------------------------------------------
// Combine split partials -> lse -> per-pair -> per-block sum; the LAST block
// (atomic ticket) tree-reduces the 32 block sums and writes the loss.
// ---------------------------------------------------------------------------
__global__ void lse_finalize(const float* __restrict__ z, float* __restrict__ out) {
    __shared__ float sh[128];
    __shared__ unsigned int s_last;
    const int i = blockIdx.x * 128 + threadIdx.x;

    float m = g_pm[i];
    #pragma unroll
    for (int s2 = 1; s2 < SPLITS; ++s2)
        m = fmaxf(m, g_pm[s2 * NROWS + i]);
    float ss = 0.0f;
    #pragma unroll
    for (int s2 = 0; s2 < SPLITS; ++s2)
        ss += g_ps[s2 * NROWS + i] * ex2f(g_pm[s2 * NROWS + i] - m);
    const float lse = (m + log2f(ss)) * LN2F;

    const bool valid = (i < NROWS - 1) && ((i & (LSEQ - 1)) != (LSEQ - 1));
    float pp = 0.0f;
    if (valid) {
        const float4* a = (const float4*)(z + (size_t)i * DDIM);
        const float4* b = (const float4*)(z + (size_t)(i + 1) * DDIM);
        float d0 = 0.0f;
        #pragma unroll 8
        for (int k = 0; k < DDIM / 4; ++k) {
            float4 x = a[k], y = b[k];
            d0 = fmaf(x.x, y.x, d0);
            d0 = fmaf(x.y, y.y, d0);
            d0 = fmaf(x.z, y.z, d0);
            d0 = fmaf(x.w, y.w, d0);
        }
        pp = lse - d0 * INV_T;
    }

    sh[threadIdx.x] = pp;
    __syncthreads();
    #pragma unroll
    for (int o = 64; o > 0; o >>= 1) {
        if (threadIdx.x < o) sh[threadIdx.x] += sh[threadIdx.x + o];
        __syncthreads();
    }
    if (threadIdx.x == 0) {
        g_bs[blockIdx.x] = sh[0];
        __threadfence();
        s_last = (atomicAdd(&g_ctr, 1u) == 31u);
    }
    __syncthreads();
    if (s_last && threadIdx.x < 32) {
        float v = g_bs[threadIdx.x];
        #pragma unroll
        for (int o = 16; o > 0; o >>= 1)
            v += __shfl_xor_sync(0xffffffffu, v, o);
        if (threadIdx.x == 0) {
            out[0] = v * (1.0f / 4080.0f);
            g_ctr = 0;                   // reset for next graph replay
        }
    }
}

// ---------------------------------------------------------------------------
extern "C" void kernel_launch(void* const* d_in, const int* in_sizes, int n_in,
                              void* d_out, int out_size) {
    const float* z   = nullptr;
    const float* mem = nullptr;
    for (int i = 0; i < n_in; ++i) {
        if (in_sizes[i] == NROWS * DDIM && !z)   z   = (const float*)d_in[i];
        if (in_sizes[i] == KMEM * DDIM  && !mem) mem = (const float*)d_in[i];
    }
    if (!z)   z   = (const float*)d_in[0];
    if (!mem) mem = (const float*)d_in[2];

    cudaFuncSetAttribute(lse_mma, cudaFuncAttributeMaxDynamicSharedMemorySize,
                         SMEM_DYN);
    prep<<<(WROWS * 16 + 255) / 256, 256>>>(z, mem);
    lse_mma<<<dim3(32, SPLITS), 256, SMEM_DYN>>>();
    lse_finalize<<<32, 128>>>(z, (float*)d_out);
}

// round 16
// speedup vs baseline: 2.0864x; 1.0997x over previous
#include <cuda_runtime.h>
#include <math.h>
#include <stdint.h>

// ---------------- problem constants ----------------
#define NROWS  4096
#define DDIM   256
#define KMEM   16384
#define ZCOLS  4096
#define WROWS  (ZCOLS + KMEM)   // 20480
#define LSEQ   256
#define SPLITS 9                // 80 col tiles of 256: 8x9 + 1x8
#define TMR    128
#define TNC    256
#define WPR    128              // words per row (bf16 packed)
#define SA     132              // A smem stride (words); ==4 mod 32
#define INV_T  (1.0f/0.07f)
#define LOG2E  1.4426950408889634f
#define LN2F   0.6931471805599453f
#define NEG_BIG (-1.0e30f)

#define SMEM_DYN (TMR * SA * 4)   // 67,584 B

// ---------------- scratch ----------------
__device__ uint32_t g_wp[(size_t)WROWS * WPR];
__device__ float g_pm[SPLITS * NROWS];
__device__ float g_ps[SPLITS * NROWS];
__device__ float g_bs[32];
__device__ unsigned int g_ctr;   // zero-init; self-resets each launch

// ---------------- helpers ----------------
__device__ __forceinline__ uint32_t packbf(float lo, float hi) {
    uint32_t r;
    asm("cvt.rn.bf16x2.f32 %0, %1, %2;" : "=r"(r) : "f"(hi), "f"(lo));
    return r;
}
__device__ __forceinline__ float ex2f(float x) {
    float r; asm("ex2.approx.f32 %0, %1;" : "=f"(r) : "f"(x)); return r;
}
__device__ __forceinline__ void mma16(float* d,
                                      uint32_t a0, uint32_t a1, uint32_t a2, uint32_t a3,
                                      uint32_t b0, uint32_t b1) {
    asm volatile(
        "mma.sync.aligned.m16n8k16.row.col.f32.bf16.bf16.f32 "
        "{%0,%1,%2,%3}, {%4,%5,%6,%7}, {%8,%9}, {%0,%1,%2,%3};"
        : "+f"(d[0]), "+f"(d[1]), "+f"(d[2]), "+f"(d[3])
        : "r"(a0), "r"(a1), "r"(a2), "r"(a3), "r"(b0), "r"(b1));
}
// first-chunk variant: C = 0 (no acc zero-init needed)
__device__ __forceinline__ void mma16z(float* d,
                                       uint32_t a0, uint32_t a1, uint32_t a2, uint32_t a3,
                                       uint32_t b0, uint32_t b1) {
    asm volatile(
        "mma.sync.aligned.m16n8k16.row.col.f32.bf16.bf16.f32 "
        "{%0,%1,%2,%3}, {%4,%5,%6,%7}, {%8,%9}, {%10,%11,%12,%13};"
        : "=f"(d[0]), "=f"(d[1]), "=f"(d[2]), "=f"(d[3])
        : "r"(a0), "r"(a1), "r"(a2), "r"(a3), "r"(b0), "r"(b1),
          "f"(0.0f), "f"(0.0f), "f"(0.0f), "f"(0.0f));
}

// ---------------------------------------------------------------------------
// Pre-pass (R12 version): bf16-convert z||mem into the lane-fragment layout.
// ---------------------------------------------------------------------------
__global__ __launch_bounds__(256)
void prep(const float* __restrict__ z, const float* __restrict__ mem) {
    const int idx = blockIdx.x * 256 + threadIdx.x;
    const int row = idx >> 4;
    const int ch  = (idx >> 1) & 7;
    const int h   = idx & 1;
    if (row >= WROWS) return;
    const float* src = ((row < ZCOLS) ? (z + (size_t)row * DDIM)
                                      : (mem + (size_t)(row - ZCOLS) * DDIM))
                       + ch * 32 + h * 4;
    float4 a0 = *(const float4*)(src);
    float4 a1 = *(const float4*)(src + 8);
    float4 a2 = *(const float4*)(src + 16);
    float4 a3 = *(const float4*)(src + 24);
    uint32_t* dst = g_wp + (size_t)row * WPR + ch * 16 + h * 8;
    uint4 o0, o1;
    o0.x = packbf(a0.x, a0.y);  o0.y = packbf(a1.x, a1.y);
    o0.z = packbf(a2.x, a2.y);  o0.w = packbf(a3.x, a3.y);
    o1.x = packbf(a0.z, a0.w);  o1.y = packbf(a1.z, a1.w);
    o1.z = packbf(a2.z, a2.w);  o1.w = packbf(a3.z, a3.w);
    *(uint4*)(dst)     = o0;
    *(uint4*)(dst + 4) = o1;
}

// ---------------------------------------------------------------------------
// Fused bf16 mma.sync GEMM + online logsumexp.
// 256 threads = 8 warps, 2(M) x 4(N); warp tile 64x64 (m16n8k16).
// Barrier-free main loop; SMSP-paired warps staggered by nt/2 tiles;
// split-pass MMA; peeled chunk 0 with C=0 (no acc zeroing); lane-local
// epilogue with f16x2 ex2 (half the MUFU ops); qc merge once at the end.
// ---------------------------------------------------------------------------
__global__ __launch_bounds__(256, 1)
void lse_mma() {
    extern __shared__ uint32_t As[];    // [128][SA]
    __shared__ float red_m[8][64];
    __shared__ float red_s[8][64];

    const int tid  = threadIdx.x;
    const int wid  = tid >> 5;
    const int lane = tid & 31;
    const int wm   = wid >> 2;          // 0..1 (M)
    const int wn   = wid & 3;           // 0..3 (N)
    const int qr   = lane >> 2;         // 0..7
    const int qc   = lane & 3;          // 0..3
    const int m0   = blockIdx.x * TMR;
    const int s    = blockIdx.y;
    const int lo   = s * 9;
    const int nt   = (s < 8) ? 9 : 8;
    const int rot  = wm ? (nt >> 1) : 0;

    const int broff = wn * 64 + qr;
    const int bwoff = qc * 4;

    // first tile chunk-0 loads issued before the A copy (complete under it)
    int ti = rot;
    const uint32_t* bp = g_wp + (size_t)((lo + ti) * TNC + broff) * WPR + bwoff;
    uint4 bq[2][8];
    #pragma unroll
    for (int ni = 0; ni < 8; ++ni)
        bq[0][ni] = *(const uint4*)(bp + ni * 8 * WPR);

    // ---- A tile copy with quad remap ----
    #pragma unroll 4
    for (int it = 0; it < 16; ++it) {
        int idx = it * 256 + tid;
        int m   = idx >> 5;
        int kq  = idx & 31;
        int d   = kq & 7;
        int sq  = (kq & ~7) | (((d & 1) << 2) | (d >> 1));
        uint4 v = *(const uint4*)(g_wp + (size_t)(m0 + m) * WPR + sq * 4);
        *(uint4*)(As + m * SA + kq * 4) = v;
    }
    __syncthreads();                    // the ONLY barrier before the end

    float rm[8], rs[8];                 // per-lane online LSE state
    #pragma unroll
    for (int i = 0; i < 8; ++i) { rm[i] = NEG_BIG; rs[i] = 0.0f; }

    const float Cs = INV_T * LOG2E;

    #pragma unroll 1
    for (int tj = 0; tj < nt; ++tj) {
        const int  c0 = (lo + ti) * TNC;
        const bool zp = (c0 < ZCOLS);

        int tn = ti + 1; if (tn >= nt) tn = 0;
        const uint32_t* bpn = g_wp + (size_t)((lo + tn) * TNC + broff) * WPR + bwoff;

        float acc[4][8][4];

        // ---- peeled k-chunk 0: pass1 writes acc with C=0 ----
        {
            // prefetch chunk 1 into bq[1]
            #pragma unroll
            for (int ni = 0; ni < 8; ++ni)
                bq[1][ni] = *(const uint4*)(bp + ni * 8 * WPR + 16);
            const int ao = qc * 8;
            uint4 aL[4], aH[4];
            #pragma unroll
            for (int mi = 0; mi < 4; ++mi) {
                const int r = wm * 64 + mi * 16 + qr;
                aL[mi] = *(const uint4*)(As + r * SA + ao);
                aH[mi] = *(const uint4*)(As + (r + 8) * SA + ao);
            }
            #pragma unroll
            for (int mi = 0; mi < 4; ++mi)
                #pragma unroll
                for (int ni = 0; ni < 8; ++ni)
                    mma16z(acc[mi][ni], aL[mi].x, aH[mi].x, aL[mi].y, aH[mi].y,
                           bq[0][ni].x, bq[0][ni].y);
            #pragma unroll
            for (int mi = 0; mi < 4; ++mi)
                #pragma unroll
                for (int ni = 0; ni < 8; ++ni)
                    mma16(acc[mi][ni], aL[mi].z, aH[mi].z, aL[mi].w, aH[mi].w,
                          bq[0][ni].z, bq[0][ni].w);
        }

        #pragma unroll 2
        for (int kc = 1; kc < 8; ++kc) {
            const int cur = kc & 1;
            if (kc < 7) {
                #pragma unroll
                for (int ni = 0; ni < 8; ++ni)
                    bq[cur ^ 1][ni] =
                        *(const uint4*)(bp + ni * 8 * WPR + (kc + 1) * 16);
            } else if (tj + 1 < nt) {
                #pragma unroll
                for (int ni = 0; ni < 8; ++ni)
                    bq[0][ni] = *(const uint4*)(bpn + ni * 8 * WPR);
            }
            const int ao = (kc >> 1) * 32 + qc * 8 + (kc & 1) * 4;
            uint4 aL[4], aH[4];
            #pragma unroll
            for (int mi = 0; mi < 4; ++mi) {
                const int r = wm * 64 + mi * 16 + qr;
                aL[mi] = *(const uint4*)(As + r * SA + ao);
                aH[mi] = *(const uint4*)(As + (r + 8) * SA + ao);
            }
            #pragma unroll
            for (int mi = 0; mi < 4; ++mi)
                #pragma unroll
                for (int ni = 0; ni < 8; ++ni)
                    mma16(acc[mi][ni], aL[mi].x, aH[mi].x, aL[mi].y, aH[mi].y,
                          bq[cur][ni].x, bq[cur][ni].y);
            #pragma unroll
            for (int mi = 0; mi < 4; ++mi)
                #pragma unroll
                for (int ni = 0; ni < 8; ++ni)
                    mma16(acc[mi][ni], aL[mi].z, aH[mi].z, aL[mi].w, aH[mi].w,
                          bq[cur][ni].z, bq[cur][ni].w);
        }

        // ---- lane-local flash-LSE epilogue with f16x2 ex2 ----
        const bool dflag = zp && (c0 == (m0 & ~(TNC - 1)));
        #pragma unroll
        for (int mi = 0; mi < 4; ++mi) {
            #pragma unroll
            for (int h = 0; h < 2; ++h) {
                const int lr   = wm * 64 + mi * 16 + h * 8 + qr;
                const int grow = m0 + lr;
                float v[16];
                float mx = NEG_BIG;
                #pragma unroll
                for (int ni = 0; ni < 8; ++ni) {
                    #pragma unroll
                    for (int c = 0; c < 2; ++c) {
                        float x = acc[mi][ni][h * 2 + c];
                        if (dflag) {
                            const int gcol = c0 + wn * 64 + ni * 8 + 2 * qc + c;
                            if (gcol == grow) x = NEG_BIG;
                        }
                        v[ni * 2 + c] = x;
                        mx = fmaxf(mx, x);
                    }
                }
                const float mxs = mx * Cs;
                uint32_t sc2 = 0;                       // f16x2 accumulator
                #pragma unroll
                for (int j = 0; j < 8; ++j) {
                    float a0 = fmaf(v[2 * j],     Cs, -mxs);
                    float a1 = fmaf(v[2 * j + 1], Cs, -mxs);
                    uint32_t p, e;
                    asm("cvt.rn.f16x2.f32 %0, %1, %2;" : "=r"(p) : "f"(a1), "f"(a0));
                    asm("ex2.approx.f16x2 %0, %1;" : "=r"(e) : "r"(p));
                    asm("add.rn.f16x2 %0, %1, %2;" : "=r"(sc2) : "r"(sc2), "r"(e));
                }
                float sLo, sHi;
                asm("{\n\t.reg .b16 l,h;\n\t"
                    "mov.b32 {l,h}, %2;\n\t"
                    "cvt.f32.f16 %0, l;\n\t"
                    "cvt.f32.f16 %1, h;\n\t}"
                    : "=f"(sLo), "=f"(sHi) : "r"(sc2));
                const float sc = sLo + sHi;
                const int ri = mi * 2 + h;
                const float mn = fmaxf(rm[ri], mxs);
                rs[ri] = rs[ri] * ex2f(rm[ri] - mn) + sc * ex2f(mxs - mn);
                rm[ri] = mn;
            }
        }

        ti = tn;
        bp = bpn;
    }

    // ---- merge the 4 qc-lanes' partial LSE states (2 butterfly steps) ----
    #pragma unroll
    for (int ri = 0; ri < 8; ++ri) {
        #pragma unroll
        for (int off = 1; off <= 2; off <<= 1) {
            float om = __shfl_xor_sync(0xffffffffu, rm[ri], off);
            float os = __shfl_xor_sync(0xffffffffu, rs[ri], off);
            float mn = fmaxf(rm[ri], om);
            rs[ri] = rs[ri] * ex2f(rm[ri] - mn) + os * ex2f(om - mn);
            rm[ri] = mn;
        }
    }

    // ---- cross-warp (N-dim) merge via smem ----
    if (qc == 0) {
        #pragma unroll
        for (int mi = 0; mi < 4; ++mi)
            #pragma unroll
            for (int h = 0; h < 2; ++h) {
                const int lrw = mi * 16 + h * 8 + qr;
                red_m[wid][lrw] = rm[mi * 2 + h];
                red_s[wid][lrw] = rs[mi * 2 + h];
            }
    }
    __syncthreads();
    if (tid < 128) {
        const int wmm = tid >> 6, ri = tid & 63;
        float m = red_m[wmm * 4][ri];
        #pragma unroll
        for (int w = 1; w < 4; ++w) m = fmaxf(m, red_m[wmm * 4 + w][ri]);
        float ss = 0.0f;
        #pragma unroll
        for (int w = 0; w < 4; ++w)
            ss += red_s[wmm * 4 + w][ri] * ex2f(red_m[wmm * 4 + w][ri] - m);
        g_pm[s * NROWS + m0 + tid] = m;
        g_ps[s * NROWS + m0 + tid] = ss;
    }
}

// ---------------------------------------------------------------------------
// Combine split partials -> lse -> per-pair -> per-block sum; the LAST block
// (atomic ticket) tree-reduces the 32 block sums and writes the loss.
// ---------------------------------------------------------------------------
__global__ void lse_finalize(const float* __restrict__ z, float* __restrict__ out) {
    __shared__ float sh[128];
    __shared__ unsigned int s_last;
    const int i = blockIdx.x * 128 + threadIdx.x;

    float m = g_pm[i];
    #pragma unroll
    for (int s2 = 1; s2 < SPLITS; ++s2)
        m = fmaxf(m, g_pm[s2 * NROWS + i]);
    float ss = 0.0f;
    #pragma unroll
    for (int s2 = 0; s2 < SPLITS; ++s2)
        ss += g_ps[s2 * NROWS + i] * ex2f(g_pm[s2 * NROWS + i] - m);
    const float lse = (m + log2f(ss)) * LN2F;

    const bool valid = (i < NROWS - 1) && ((i & (LSEQ - 1)) != (LSEQ - 1));
    float pp = 0.0f;
    if (valid) {
        const float4* a = (const float4*)(z + (size_t)i * DDIM);
        const float4* b = (const float4*)(z + (size_t)(i + 1) * DDIM);
        float d0 = 0.0f;
        #pragma unroll 8
        for (int k = 0; k < DDIM / 4; ++k) {
            float4 x = a[k], y = b[k];
            d0 = fmaf(x.x, y.x, d0);
            d0 = fmaf(x.y, y.y, d0);
            d0 = fmaf(x.z, y.z, d0);
            d0 = fmaf(x.w, y.w, d0);
        }
        pp = lse - d0 * INV_T;
    }

    sh[threadIdx.x] = pp;
    __syncthreads();
    #pragma unroll
    for (int o = 64; o > 0; o >>= 1) {
        if (threadIdx.x < o) sh[threadIdx.x] += sh[threadIdx.x + o];
        __syncthreads();
    }
    if (threadIdx.x == 0) {
        g_bs[blockIdx.x] = sh[0];
        __threadfence();
        s_last = (atomicAdd(&g_ctr, 1u) == 31u);
    }
    __syncthreads();
    if (s_last && threadIdx.x < 32) {
        float v = g_bs[threadIdx.x];
        #pragma unroll
        for (int o = 16; o > 0; o >>= 1)
            v += __shfl_xor_sync(0xffffffffu, v, o);
        if (threadIdx.x == 0) {
            out[0] = v * (1.0f / 4080.0f);
            g_ctr = 0;                   // reset for next graph replay
        }
    }
}

// ---------------------------------------------------------------------------
extern "C" void kernel_launch(void* const* d_in, const int* in_sizes, int n_in,
                              void* d_out, int out_size) {
    const float* z   = nullptr;
    const float* mem = nullptr;
    for (int i = 0; i < n_in; ++i) {
        if (in_sizes[i] == NROWS * DDIM && !z)   z   = (const float*)d_in[i];
        if (in_sizes[i] == KMEM * DDIM  && !mem) mem = (const float*)d_in[i];
    }
    if (!z)   z   = (const float*)d_in[0];
    if (!mem) mem = (const float*)d_in[2];

    cudaFuncSetAttribute(lse_mma, cudaFuncAttributeMaxDynamicSharedMemorySize,
                         SMEM_DYN);
    prep<<<(WROWS * 16 + 255) / 256, 256>>>(z, mem);
    lse_mma<<<dim3(32, SPLITS), 256, SMEM_DYN>>>();
    lse_finalize<<<32, 128>>>(z, (float*)d_out);
}